// round 9
// baseline (speedup 1.0000x reference)
#include <cuda_runtime.h>

typedef unsigned long long ull;

#define N_REC   200
#define N_INP   10
#define BATCH   256
#define TSTEPS  1000
#define TOTAL_ELEMS 51200000u   // T*B*N

// drive[t][b][r] = { inp_term(t,b,r),  0.01f * normal(t,b,r) }
static __device__ float2 g_drive[TOTAL_ELEMS];

// ---------------------------------------------------------------------------
// helpers
// ---------------------------------------------------------------------------
__device__ __forceinline__ ull ffma2(ull a, ull b, ull c) {
    ull d;
    asm("fma.rn.f32x2 %0, %1, %2, %3;" : "=l"(d) : "l"(a), "l"(b), "l"(c));
    return d;
}
__device__ __forceinline__ float lo32f(ull v) { return __uint_as_float((unsigned)v); }
__device__ __forceinline__ float hi32f(ull v) { return __uint_as_float((unsigned)(v >> 32)); }

__device__ __forceinline__ unsigned rotl32(unsigned v, int s) {
    return __funnelshift_l(v, v, s);
}

// Threefry-2x32/20, key=(0,42), partitionable: counter=(0,p), out = x0^x1.
__device__ __forceinline__ unsigned threefry_bits(unsigned p) {
    const unsigned k0 = 0u;
    const unsigned k1 = 42u;
    const unsigned k2 = 0x1BD11BDAu ^ 0u ^ 42u;
    unsigned x0 = 0u + k0;
    unsigned x1 = p + k1;
#define TFR(rr) { x0 += x1; x1 = rotl32(x1, rr); x1 ^= x0; }
    TFR(13) TFR(15) TFR(26) TFR(6)   x0 += k1; x1 += k2 + 1u;
    TFR(17) TFR(29) TFR(16) TFR(24)  x0 += k2; x1 += k0 + 2u;
    TFR(13) TFR(15) TFR(26) TFR(6)   x0 += k0; x1 += k1 + 3u;
    TFR(17) TFR(29) TFR(16) TFR(24)  x0 += k1; x1 += k2 + 4u;
    TFR(13) TFR(15) TFR(26) TFR(6)   x0 += k2; x1 += k0 + 5u;
#undef TFR
    return x0 ^ x1;
}

// ---------------------------------------------------------------------------
// Pre-kernel: drive[t][b][r] = (x[b,t,:]·W_inp[r,:] + b_rec[r], 0.01*N(0,1))
// W_inp / b_rec cached in smem (cuts ~11 LDG per element).
// ---------------------------------------------------------------------------
__global__ void gen_drive_kernel(const float* __restrict__ x,
                                 const float* __restrict__ W_inp,
                                 const float* __restrict__ b_rec) {
    __shared__ float sW[N_REC * N_INP];
    __shared__ float sB[N_REC];
    for (int i = threadIdx.x; i < N_REC * N_INP; i += blockDim.x) sW[i] = W_inp[i];
    for (int i = threadIdx.x; i < N_REC; i += blockDim.x)        sB[i] = b_rec[i];
    __syncthreads();

    unsigned p = blockIdx.x * blockDim.x + threadIdx.x;
    if (p >= TOTAL_ELEMS) return;

    unsigned bits = threefry_bits(p);
    float f = __uint_as_float((bits >> 9) | 0x3f800000u) - 1.0f;   // [0,1)
    const float lo = __uint_as_float(0xbf7fffffu);                 // nextafter(-1,0)
    float u = fmaf(f, 2.0f, lo);
    u = fmaxf(u, lo);
    float n = __uint_as_float(0x3fb504f3u) * erfinvf(u);           // sqrt(2)*erfinv

    unsigned r  = p % 200u;
    unsigned bt = p / 200u;
    unsigned b  = bt & 255u;
    unsigned t  = bt >> 8;
    const float* xr = x + (b * (unsigned)TSTEPS + t) * (unsigned)N_INP;
    float inp = sB[r];
#pragma unroll
    for (int i = 0; i < N_INP; ++i)
        inp = fmaf(__ldg(xr + i), sW[r * N_INP + i], inp);

    g_drive[p] = make_float2(inp, 0.01f * n);
}

// ---------------------------------------------------------------------------
// Main persistent RNN kernel: 128 blocks x 800 threads (25 warps, ~80 reg cap).
// Thread = (r = tid>>2, kq = tid&3); holds W_rec[r, kq*50..+50) in 50 regs.
// h stored per-kq-slice, padded to 56 floats for 16B alignment + disjoint banks.
// Reduction across kq nibble via 2x shfl_xor.
// ---------------------------------------------------------------------------
__global__ __launch_bounds__(800, 1)
void rnn_kernel(const float* __restrict__ h0,
                const float* __restrict__ Wrec,
                float* __restrict__ out) {
    // [buf][row-in-pair][4 slices * 56 floats]
    __shared__ __align__(16) float hsf[2][2][224];

    const int tid = threadIdx.x;
    const int r   = tid >> 2;     // 0..199
    const int kq  = tid & 3;      // 0..3
    const int b0  = blockIdx.x * 2;

    // ---- W_rec slice: 50 floats = 25 f32x2 regs (8B-aligned loads) ----
    ull w[25];
    {
        const ull* wp = reinterpret_cast<const ull*>(Wrec + r * N_REC + kq * 50);
#pragma unroll
        for (int j = 0; j < 25; ++j) w[j] = wp[j];
    }

    // write slot for hnew (k index r lives in slice r/50, padded stride 56)
    const int ws = (r / 50) * 56 + (r % 50);
    const int rb = kq * 56;       // read base of this thread's k slice

    float hold0 = 0.f, hold1 = 0.f;
    float2 dr0 = make_float2(0.f, 0.f), dr1 = make_float2(0.f, 0.f);
    if (kq == 0) {
        hold0 = h0[(b0 + 0) * N_REC + r];
        hold1 = h0[(b0 + 1) * N_REC + r];
        hsf[0][0][ws] = hold0;
        hsf[0][1][ws] = hold1;
        dr0 = g_drive[((unsigned)b0)      * (unsigned)N_REC + (unsigned)r];
        dr1 = g_drive[((unsigned)b0 + 1u) * (unsigned)N_REC + (unsigned)r];
    }
    __syncthreads();

    float* outp0 = out + (size_t)(b0 + 0) * (TSTEPS * N_REC) + r;
    float* outp1 = out + (size_t)(b0 + 1) * (TSTEPS * N_REC) + r;

    int p = 0;
    for (int t = 0; t < TSTEPS; ++t) {
        const float* h0p = &hsf[p][0][rb];
        const float* h1p = &hsf[p][1][rb];
        const ulonglong2* ha = reinterpret_cast<const ulonglong2*>(h0p);
        const ulonglong2* hb = reinterpret_cast<const ulonglong2*>(h1p);

        ull acc0 = 0ull, acc1 = 0ull;
#pragma unroll
        for (int j = 0; j < 12; ++j) {
            ulonglong2 va = ha[j];
            ulonglong2 vb = hb[j];
            acc0 = ffma2(w[2 * j],     va.x, acc0);
            acc0 = ffma2(w[2 * j + 1], va.y, acc0);
            acc1 = ffma2(w[2 * j],     vb.x, acc1);
            acc1 = ffma2(w[2 * j + 1], vb.y, acc1);
        }
        // tail: k elements 48,49 of the slice
        {
            ull ta = reinterpret_cast<const ull*>(h0p)[24];
            ull tb = reinterpret_cast<const ull*>(h1p)[24];
            acc0 = ffma2(w[24], ta, acc0);
            acc1 = ffma2(w[24], tb, acc1);
        }

        float s0 = lo32f(acc0) + hi32f(acc0);
        float s1 = lo32f(acc1) + hi32f(acc1);
        s0 += __shfl_xor_sync(0xffffffffu, s0, 1);
        s0 += __shfl_xor_sync(0xffffffffu, s0, 2);
        s1 += __shfl_xor_sync(0xffffffffu, s1, 1);
        s1 += __shfl_xor_sync(0xffffffffu, s1, 2);

        if (kq == 0) {
            float rate0 = tanhf(s0 + dr0.x);
            float rate1 = tanhf(s1 + dr1.x);
            hold0 = fmaf(0.1f, (rate0 - hold0) + dr0.y, hold0);
            hold1 = fmaf(0.1f, (rate1 - hold1) + dr1.y, hold1);
            hsf[p ^ 1][0][ws] = hold0;
            hsf[p ^ 1][1][ws] = hold1;
            outp0[t * N_REC] = hold0;
            outp1[t * N_REC] = hold1;
            unsigned tn = (t < TSTEPS - 1) ? (unsigned)(t + 1) : (unsigned)(TSTEPS - 1);
            dr0 = g_drive[(tn * BATCH + (unsigned)b0)      * (unsigned)N_REC + (unsigned)r];
            dr1 = g_drive[(tn * BATCH + (unsigned)b0 + 1u) * (unsigned)N_REC + (unsigned)r];
        }
        p ^= 1;
        __syncthreads();
    }
}

// ---------------------------------------------------------------------------
extern "C" void kernel_launch(void* const* d_in, const int* in_sizes, int n_in,
                              void* d_out, int out_size) {
    const float* x     = (const float*)d_in[0];   // [256,1000,10]
    const float* h0    = (const float*)d_in[1];   // [256,200]
    const float* W_inp = (const float*)d_in[2];   // [200,10]
    const float* W_rec = (const float*)d_in[3];   // [200,200]
    const float* b_rec = (const float*)d_in[4];   // [200]
    float* out = (float*)d_out;                   // [256,1000,200]

    gen_drive_kernel<<<TOTAL_ELEMS / 256u, 256>>>(x, W_inp, b_rec);
    rnn_kernel<<<BATCH / 2, 800>>>(h0, W_rec, out);
}

// round 10
// speedup vs baseline: 1.0001x; 1.0001x over previous
#include <cuda_runtime.h>

typedef unsigned long long ull;

#define N_REC   200
#define N_INP   10
#define BATCH   256
#define TSTEPS  1000
#define TOTAL_ELEMS 51200000u   // T*B*N

// drive[t][b][r] = { inp_term(t,b,r),  0.01f * normal(t,b,r) }
static __device__ float2 g_drive[TOTAL_ELEMS];

// ---------------------------------------------------------------------------
// helpers
// ---------------------------------------------------------------------------
__device__ __forceinline__ ull ffma2(ull a, ull b, ull c) {
    ull d;
    asm("fma.rn.f32x2 %0, %1, %2, %3;" : "=l"(d) : "l"(a), "l"(b), "l"(c));
    return d;
}
__device__ __forceinline__ float lo32f(ull v) { return __uint_as_float((unsigned)v); }
__device__ __forceinline__ float hi32f(ull v) { return __uint_as_float((unsigned)(v >> 32)); }

__device__ __forceinline__ unsigned rotl32(unsigned v, int s) {
    return __funnelshift_l(v, v, s);
}

// Threefry-2x32/20, key=(0,42), partitionable: counter=(0,p), out = x0^x1.
__device__ __forceinline__ unsigned threefry_bits(unsigned p) {
    const unsigned k0 = 0u;
    const unsigned k1 = 42u;
    const unsigned k2 = 0x1BD11BDAu ^ 0u ^ 42u;
    unsigned x0 = 0u + k0;
    unsigned x1 = p + k1;
#define TFR(rr) { x0 += x1; x1 = rotl32(x1, rr); x1 ^= x0; }
    TFR(13) TFR(15) TFR(26) TFR(6)   x0 += k1; x1 += k2 + 1u;
    TFR(17) TFR(29) TFR(16) TFR(24)  x0 += k2; x1 += k0 + 2u;
    TFR(13) TFR(15) TFR(26) TFR(6)   x0 += k0; x1 += k1 + 3u;
    TFR(17) TFR(29) TFR(16) TFR(24)  x0 += k1; x1 += k2 + 4u;
    TFR(13) TFR(15) TFR(26) TFR(6)   x0 += k2; x1 += k0 + 5u;
#undef TFR
    return x0 ^ x1;
}

// ---------------------------------------------------------------------------
// Pre-kernel: drive[t][b][r] = (x[b,t,:]·W_inp[r,:] + b_rec[r], 0.01*N(0,1))
// W_inp / b_rec cached in smem (cuts ~11 LDG per element).
// ---------------------------------------------------------------------------
__global__ void gen_drive_kernel(const float* __restrict__ x,
                                 const float* __restrict__ W_inp,
                                 const float* __restrict__ b_rec) {
    __shared__ float sW[N_REC * N_INP];
    __shared__ float sB[N_REC];
    for (int i = threadIdx.x; i < N_REC * N_INP; i += blockDim.x) sW[i] = W_inp[i];
    for (int i = threadIdx.x; i < N_REC; i += blockDim.x)        sB[i] = b_rec[i];
    __syncthreads();

    unsigned p = blockIdx.x * blockDim.x + threadIdx.x;
    if (p >= TOTAL_ELEMS) return;

    unsigned bits = threefry_bits(p);
    float f = __uint_as_float((bits >> 9) | 0x3f800000u) - 1.0f;   // [0,1)
    const float lo = __uint_as_float(0xbf7fffffu);                 // nextafter(-1,0)
    float u = fmaf(f, 2.0f, lo);
    u = fmaxf(u, lo);
    float n = __uint_as_float(0x3fb504f3u) * erfinvf(u);           // sqrt(2)*erfinv

    unsigned r  = p % 200u;
    unsigned bt = p / 200u;
    unsigned b  = bt & 255u;
    unsigned t  = bt >> 8;
    const float* xr = x + (b * (unsigned)TSTEPS + t) * (unsigned)N_INP;
    float inp = sB[r];
#pragma unroll
    for (int i = 0; i < N_INP; ++i)
        inp = fmaf(__ldg(xr + i), sW[r * N_INP + i], inp);

    g_drive[p] = make_float2(inp, 0.01f * n);
}

// ---------------------------------------------------------------------------
// Main persistent RNN kernel: 128 blocks x 800 threads (25 warps, ~80 reg cap).
// Thread = (r = tid>>2, kq = tid&3); holds W_rec[r, kq*50..+50) in 50 regs.
// h stored per-kq-slice, padded to 56 floats for 16B alignment + disjoint banks.
// Reduction across kq nibble via 2x shfl_xor.
// ---------------------------------------------------------------------------
__global__ __launch_bounds__(800, 1)
void rnn_kernel(const float* __restrict__ h0,
                const float* __restrict__ Wrec,
                float* __restrict__ out) {
    // [buf][row-in-pair][4 slices * 56 floats]
    __shared__ __align__(16) float hsf[2][2][224];

    const int tid = threadIdx.x;
    const int r   = tid >> 2;     // 0..199
    const int kq  = tid & 3;      // 0..3
    const int b0  = blockIdx.x * 2;

    // ---- W_rec slice: 50 floats = 25 f32x2 regs (8B-aligned loads) ----
    ull w[25];
    {
        const ull* wp = reinterpret_cast<const ull*>(Wrec + r * N_REC + kq * 50);
#pragma unroll
        for (int j = 0; j < 25; ++j) w[j] = wp[j];
    }

    // write slot for hnew (k index r lives in slice r/50, padded stride 56)
    const int ws = (r / 50) * 56 + (r % 50);
    const int rb = kq * 56;       // read base of this thread's k slice

    float hold0 = 0.f, hold1 = 0.f;
    float2 dr0 = make_float2(0.f, 0.f), dr1 = make_float2(0.f, 0.f);
    if (kq == 0) {
        hold0 = h0[(b0 + 0) * N_REC + r];
        hold1 = h0[(b0 + 1) * N_REC + r];
        hsf[0][0][ws] = hold0;
        hsf[0][1][ws] = hold1;
        dr0 = g_drive[((unsigned)b0)      * (unsigned)N_REC + (unsigned)r];
        dr1 = g_drive[((unsigned)b0 + 1u) * (unsigned)N_REC + (unsigned)r];
    }
    __syncthreads();

    float* outp0 = out + (size_t)(b0 + 0) * (TSTEPS * N_REC) + r;
    float* outp1 = out + (size_t)(b0 + 1) * (TSTEPS * N_REC) + r;

    int p = 0;
    for (int t = 0; t < TSTEPS; ++t) {
        const float* h0p = &hsf[p][0][rb];
        const float* h1p = &hsf[p][1][rb];
        const ulonglong2* ha = reinterpret_cast<const ulonglong2*>(h0p);
        const ulonglong2* hb = reinterpret_cast<const ulonglong2*>(h1p);

        ull acc0 = 0ull, acc1 = 0ull;
#pragma unroll
        for (int j = 0; j < 12; ++j) {
            ulonglong2 va = ha[j];
            ulonglong2 vb = hb[j];
            acc0 = ffma2(w[2 * j],     va.x, acc0);
            acc0 = ffma2(w[2 * j + 1], va.y, acc0);
            acc1 = ffma2(w[2 * j],     vb.x, acc1);
            acc1 = ffma2(w[2 * j + 1], vb.y, acc1);
        }
        // tail: k elements 48,49 of the slice
        {
            ull ta = reinterpret_cast<const ull*>(h0p)[24];
            ull tb = reinterpret_cast<const ull*>(h1p)[24];
            acc0 = ffma2(w[24], ta, acc0);
            acc1 = ffma2(w[24], tb, acc1);
        }

        float s0 = lo32f(acc0) + hi32f(acc0);
        float s1 = lo32f(acc1) + hi32f(acc1);
        s0 += __shfl_xor_sync(0xffffffffu, s0, 1);
        s0 += __shfl_xor_sync(0xffffffffu, s0, 2);
        s1 += __shfl_xor_sync(0xffffffffu, s1, 1);
        s1 += __shfl_xor_sync(0xffffffffu, s1, 2);

        if (kq == 0) {
            float rate0 = tanhf(s0 + dr0.x);
            float rate1 = tanhf(s1 + dr1.x);
            hold0 = fmaf(0.1f, (rate0 - hold0) + dr0.y, hold0);
            hold1 = fmaf(0.1f, (rate1 - hold1) + dr1.y, hold1);
            hsf[p ^ 1][0][ws] = hold0;
            hsf[p ^ 1][1][ws] = hold1;
            outp0[t * N_REC] = hold0;
            outp1[t * N_REC] = hold1;
            unsigned tn = (t < TSTEPS - 1) ? (unsigned)(t + 1) : (unsigned)(TSTEPS - 1);
            dr0 = g_drive[(tn * BATCH + (unsigned)b0)      * (unsigned)N_REC + (unsigned)r];
            dr1 = g_drive[(tn * BATCH + (unsigned)b0 + 1u) * (unsigned)N_REC + (unsigned)r];
        }
        p ^= 1;
        __syncthreads();
    }
}

// ---------------------------------------------------------------------------
extern "C" void kernel_launch(void* const* d_in, const int* in_sizes, int n_in,
                              void* d_out, int out_size) {
    const float* x     = (const float*)d_in[0];   // [256,1000,10]
    const float* h0    = (const float*)d_in[1];   // [256,200]
    const float* W_inp = (const float*)d_in[2];   // [200,10]
    const float* W_rec = (const float*)d_in[3];   // [200,200]
    const float* b_rec = (const float*)d_in[4];   // [200]
    float* out = (float*)d_out;                   // [256,1000,200]

    gen_drive_kernel<<<TOTAL_ELEMS / 256u, 256>>>(x, W_inp, b_rec);
    rnn_kernel<<<BATCH / 2, 800>>>(h0, W_rec, out);
}

// round 11
// speedup vs baseline: 1.1799x; 1.1798x over previous
#include <cuda_runtime.h>

typedef unsigned long long ull;

#define N_REC   200
#define N_INP   10
#define BATCH   256
#define TSTEPS  1000
#define TOTAL_ELEMS 51200000u   // T*B*N

// drive[t][b][r] = { inp_term(t,b,r),  0.01f * normal(t,b,r) }
static __device__ float2 g_drive[TOTAL_ELEMS];

// ---------------------------------------------------------------------------
// helpers
// ---------------------------------------------------------------------------
__device__ __forceinline__ ull ffma2(ull a, ull b, ull c) {
    ull d;
    asm("fma.rn.f32x2 %0, %1, %2, %3;" : "=l"(d) : "l"(a), "l"(b), "l"(c));
    return d;
}
__device__ __forceinline__ float lo32f(ull v) { return __uint_as_float((unsigned)v); }
__device__ __forceinline__ float hi32f(ull v) { return __uint_as_float((unsigned)(v >> 32)); }

__device__ __forceinline__ unsigned rotl32(unsigned v, int s) {
    return __funnelshift_l(v, v, s);
}

// Threefry-2x32/20, key=(0,42), partitionable: counter=(0,p), out = x0^x1.
__device__ __forceinline__ unsigned threefry_bits(unsigned p) {
    const unsigned k0 = 0u;
    const unsigned k1 = 42u;
    const unsigned k2 = 0x1BD11BDAu ^ 0u ^ 42u;
    unsigned x0 = 0u + k0;
    unsigned x1 = p + k1;
#define TFR(rr) { x0 += x1; x1 = rotl32(x1, rr); x1 ^= x0; }
    TFR(13) TFR(15) TFR(26) TFR(6)   x0 += k1; x1 += k2 + 1u;
    TFR(17) TFR(29) TFR(16) TFR(24)  x0 += k2; x1 += k0 + 2u;
    TFR(13) TFR(15) TFR(26) TFR(6)   x0 += k0; x1 += k1 + 3u;
    TFR(17) TFR(29) TFR(16) TFR(24)  x0 += k1; x1 += k2 + 4u;
    TFR(13) TFR(15) TFR(26) TFR(6)   x0 += k2; x1 += k0 + 5u;
#undef TFR
    return x0 ^ x1;
}

__device__ __forceinline__ float gauss_from_bits(unsigned bits) {
    float f = __uint_as_float((bits >> 9) | 0x3f800000u) - 1.0f;   // [0,1)
    const float lo = __uint_as_float(0xbf7fffffu);                 // nextafter(-1,0)
    float u = fmaf(f, 2.0f, lo);
    u = fmaxf(u, lo);
    return __uint_as_float(0x3fb504f3u) * erfinvf(u);              // sqrt(2)*erfinv
}

// ---------------------------------------------------------------------------
// Pre-kernel: 2 elements per thread (same (b,t) pair -> shared x row),
// float4 store. drive[p] = (x·W_inp[r]+b_rec[r], 0.01*N(0,1)).
// ---------------------------------------------------------------------------
__global__ void gen_drive_kernel(const float* __restrict__ x,
                                 const float* __restrict__ W_inp,
                                 const float* __restrict__ b_rec) {
    unsigned i = blockIdx.x * blockDim.x + threadIdx.x;
    if (i >= TOTAL_ELEMS / 2u) return;
    unsigned p0 = 2u * i;

    float n0 = gauss_from_bits(threefry_bits(p0));
    float n1 = gauss_from_bits(threefry_bits(p0 + 1u));

    unsigned r0 = p0 % 200u;          // even, so r0+1 stays in same (b,t)
    unsigned bt = p0 / 200u;
    unsigned b  = bt & 255u;
    unsigned t  = bt >> 8;

    const float* xr  = x + (b * (unsigned)TSTEPS + t) * (unsigned)N_INP;
    const float* wr0 = W_inp + r0 * (unsigned)N_INP;
    const float* wr1 = wr0 + N_INP;

    float xv[N_INP];
#pragma unroll
    for (int k = 0; k < N_INP; ++k) xv[k] = __ldg(xr + k);

    float inp0 = __ldg(b_rec + r0);
    float inp1 = __ldg(b_rec + r0 + 1);
#pragma unroll
    for (int k = 0; k < N_INP; ++k) {
        inp0 = fmaf(xv[k], __ldg(wr0 + k), inp0);
        inp1 = fmaf(xv[k], __ldg(wr1 + k), inp1);
    }

    float4 st = make_float4(inp0, 0.01f * n0, inp1, 0.01f * n1);
    reinterpret_cast<float4*>(g_drive)[i] = st;
}

// ---------------------------------------------------------------------------
// Main persistent RNN kernel: 128 blocks x 448 threads.
// Warp-uniform k-halves: group g = (tid >= 224), lane index rl = tid - g*224.
// Lane holds W_rec[rl, g*100 .. +100) in 100 regs; every inner-loop LDS is a
// 32-lane broadcast (1 wavefront). Cross-group reduction via smem partials;
// group g runs the epilogue (tanh/update/store) for batch row b0+g.
// ---------------------------------------------------------------------------
__global__ __launch_bounds__(448, 1)
void rnn_kernel(const float* __restrict__ h0,
                const float* __restrict__ Wrec,
                float* __restrict__ out) {
    __shared__ __align__(16) float  hs[2][224];    // [row][r]  (single buffer)
    __shared__ __align__(8)  float2 par[2][224];   // [row][r] = {partial_g0, partial_g1}

    const int tid = threadIdx.x;
    const int g   = (tid >= 224) ? 1 : 0;   // k-half, also epilogue row
    const int rl  = tid - g * 224;          // 0..223
    const bool act = (rl < N_REC);
    const int rc  = act ? rl : (N_REC - 1);
    const int b0  = blockIdx.x * 2;
    const int brow = b0 + g;

    // ---- W_rec[rc, g*100 .. +100) -> 50 ull regs (16B vector loads) ----
    ull w[50];
    {
        const ulonglong2* wp =
            reinterpret_cast<const ulonglong2*>(Wrec + rc * N_REC + g * 100);
#pragma unroll
        for (int j = 0; j < 25; ++j) {
            ulonglong2 v = wp[j];
            w[2 * j]     = v.x;
            w[2 * j + 1] = v.y;
        }
    }

    // ---- init: group g owns h and drive for batch row b0+g ----
    float hold = act ? h0[brow * N_REC + rl] : 0.f;
    hs[g][rl] = hold;
    float2 dr = make_float2(0.f, 0.f);
    if (act) dr = g_drive[(unsigned)brow * (unsigned)N_REC + (unsigned)rl];
    __syncthreads();

    float* outp = out + (size_t)brow * (TSTEPS * N_REC) + rl;
    const ulonglong2* ha = reinterpret_cast<const ulonglong2*>(&hs[0][g * 100]);
    const ulonglong2* hb = reinterpret_cast<const ulonglong2*>(&hs[1][g * 100]);

    for (int t = 0; t < TSTEPS; ++t) {
        // ---- partial dot over this warp-group's k-half, both batch rows ----
        ull a0 = 0ull, a1 = 0ull, c0 = 0ull, c1 = 0ull;
#pragma unroll
        for (int j = 0; j < 25; ++j) {
            ulonglong2 va = ha[j];   // warp-uniform -> broadcast, 1 wavefront
            ulonglong2 vb = hb[j];
            if (j & 1) {
                a1 = ffma2(w[2 * j],     va.x, a1);
                a1 = ffma2(w[2 * j + 1], va.y, a1);
                c1 = ffma2(w[2 * j],     vb.x, c1);
                c1 = ffma2(w[2 * j + 1], vb.y, c1);
            } else {
                a0 = ffma2(w[2 * j],     va.x, a0);
                a0 = ffma2(w[2 * j + 1], va.y, a0);
                c0 = ffma2(w[2 * j],     vb.x, c0);
                c0 = ffma2(w[2 * j + 1], vb.y, c0);
            }
        }
        float s0 = (lo32f(a0) + hi32f(a0)) + (lo32f(a1) + hi32f(a1));
        float s1 = (lo32f(c0) + hi32f(c0)) + (lo32f(c1) + hi32f(c1));
        (&par[0][rl].x)[g] = s0;
        (&par[1][rl].x)[g] = s1;
        __syncthreads();

        // ---- epilogue: group g updates batch row b0+g ----
        float2 pp = par[g][rl];
        float s = (pp.x + pp.y) + dr.x;
        // tanh(s) = 1 - 2/(exp(2s)+1)  (handles +/-inf naturally)
        float e = __expf(s + s);
        float rate = 1.0f - __fdividef(2.0f, e + 1.0f);
        hold = fmaf(0.1f, (rate - hold) + dr.y, hold);
        hs[g][rl] = hold;
        if (act) {
            outp[t * N_REC] = hold;
            unsigned tn = (t < TSTEPS - 1) ? (unsigned)(t + 1) : (unsigned)(TSTEPS - 1);
            dr = g_drive[(tn * BATCH + (unsigned)brow) * (unsigned)N_REC + (unsigned)rl];
        }
        __syncthreads();
    }
}

// ---------------------------------------------------------------------------
extern "C" void kernel_launch(void* const* d_in, const int* in_sizes, int n_in,
                              void* d_out, int out_size) {
    const float* x     = (const float*)d_in[0];   // [256,1000,10]
    const float* h0    = (const float*)d_in[1];   // [256,200]
    const float* W_inp = (const float*)d_in[2];   // [200,10]
    const float* W_rec = (const float*)d_in[3];   // [200,200]
    const float* b_rec = (const float*)d_in[4];   // [200]
    float* out = (float*)d_out;                   // [256,1000,200]

    gen_drive_kernel<<<(TOTAL_ELEMS / 2u + 255u) / 256u, 256>>>(x, W_inp, b_rec);
    rnn_kernel<<<BATCH / 2, 448>>>(h0, W_rec, out);
}

// round 12
// speedup vs baseline: 1.5669x; 1.3280x over previous
#include <cuda_runtime.h>

typedef unsigned long long ull;

#define N_REC   200
#define N_INP   10
#define BATCH   256
#define TSTEPS  1000
#define TOTAL_ELEMS 51200000u   // T*B*N

// drive[t][b][r] = { inp_term(t,b,r),  0.01f * normal(t,b,r) }
static __device__ float2 g_drive[TOTAL_ELEMS];

// ---------------------------------------------------------------------------
// helpers
// ---------------------------------------------------------------------------
__device__ __forceinline__ ull ffma2(ull a, ull b, ull c) {
    ull d;
    asm("fma.rn.f32x2 %0, %1, %2, %3;" : "=l"(d) : "l"(a), "l"(b), "l"(c));
    return d;
}
__device__ __forceinline__ float lo32f(ull v) { return __uint_as_float((unsigned)v); }
__device__ __forceinline__ float hi32f(ull v) { return __uint_as_float((unsigned)(v >> 32)); }

__device__ __forceinline__ unsigned rotl32(unsigned v, int s) {
    return __funnelshift_l(v, v, s);
}

// Threefry-2x32/20, key=(0,42), partitionable: counter=(0,p), out = x0^x1.
__device__ __forceinline__ unsigned threefry_bits(unsigned p) {
    const unsigned k0 = 0u;
    const unsigned k1 = 42u;
    const unsigned k2 = 0x1BD11BDAu ^ 0u ^ 42u;
    unsigned x0 = 0u + k0;
    unsigned x1 = p + k1;
#define TFR(rr) { x0 += x1; x1 = rotl32(x1, rr); x1 ^= x0; }
    TFR(13) TFR(15) TFR(26) TFR(6)   x0 += k1; x1 += k2 + 1u;
    TFR(17) TFR(29) TFR(16) TFR(24)  x0 += k2; x1 += k0 + 2u;
    TFR(13) TFR(15) TFR(26) TFR(6)   x0 += k0; x1 += k1 + 3u;
    TFR(17) TFR(29) TFR(16) TFR(24)  x0 += k1; x1 += k2 + 4u;
    TFR(13) TFR(15) TFR(26) TFR(6)   x0 += k2; x1 += k0 + 5u;
#undef TFR
    return x0 ^ x1;
}

// ---------------------------------------------------------------------------
// Pre-kernel (reverted to the fastest measured variant: 1 elem/thread,
// no smem cache): drive[p] = (x·W_inp[r]+b_rec[r], 0.01*N(0,1)).
// ---------------------------------------------------------------------------
__global__ void gen_drive_kernel(const float* __restrict__ x,
                                 const float* __restrict__ W_inp,
                                 const float* __restrict__ b_rec) {
    unsigned p = blockIdx.x * blockDim.x + threadIdx.x;
    if (p >= TOTAL_ELEMS) return;

    unsigned bits = threefry_bits(p);
    float f = __uint_as_float((bits >> 9) | 0x3f800000u) - 1.0f;   // [0,1)
    const float lo = __uint_as_float(0xbf7fffffu);                 // nextafter(-1,0)
    float u = fmaf(f, 2.0f, lo);
    u = fmaxf(u, lo);
    float n = __uint_as_float(0x3fb504f3u) * erfinvf(u);           // sqrt(2)*erfinv

    unsigned r  = p % 200u;
    unsigned bt = p / 200u;
    unsigned b  = bt & 255u;
    unsigned t  = bt >> 8;
    const float* xr = x + (b * (unsigned)TSTEPS + t) * (unsigned)N_INP;
    const float* wr = W_inp + r * (unsigned)N_INP;
    float inp = __ldg(b_rec + r);
#pragma unroll
    for (int i = 0; i < N_INP; ++i)
        inp = fmaf(__ldg(xr + i), __ldg(wr + i), inp);

    g_drive[p] = make_float2(inp, 0.01f * n);
}

// ---------------------------------------------------------------------------
// Main persistent RNN kernel: 128 blocks x 896 threads (28 warps, 73-reg cap).
// 4 warp-aligned k-groups of 7 warps: g = tid/224, lane rl = tid%224.
// Lane holds W_rec[rl, g*50..+50) in 25 ull regs. h stored in 56-float padded
// slices (16B aligned) -> every inner LDS is a warp-uniform broadcast.
// Partials via par[row][g][rl] (conflict-free); groups 0/1 run the epilogue
// for batch rows b0+0 / b0+1.
// ---------------------------------------------------------------------------
__global__ __launch_bounds__(896, 1)
void rnn_kernel(const float* __restrict__ h0,
                const float* __restrict__ Wrec,
                float* __restrict__ out) {
    __shared__ __align__(16) float hs[2][224];       // [row][slice(rl/50)*56 + rl%50]
    __shared__ __align__(16) float par[2][4][224];   // [row][kgroup][rl]

    const int tid = threadIdx.x;
    const int g   = tid / 224;          // k-group 0..3 (7 warps each)
    const int rl  = tid - g * 224;      // 0..223
    const bool act = (rl < N_REC);
    const int rc  = act ? rl : (N_REC - 1);
    const int b0  = blockIdx.x * 2;

    // ---- W_rec[rc, g*50 .. +50) -> 25 ull regs (8B loads; base 8B-aligned) ----
    ull w[25];
    {
        const ull* wp = reinterpret_cast<const ull*>(Wrec + rc * N_REC + g * 50);
#pragma unroll
        for (int j = 0; j < 25; ++j) w[j] = wp[j];
    }

    // write slot in padded-slice layout for h[rl]
    const int ws = (rc / 50) * 56 + (rc % 50);

    // ---- init: groups 0/1 own batch rows b0+0 / b0+1 ----
    float hold = 0.f;
    float2 dr = make_float2(0.f, 0.f);
    const int erow = g;                 // epilogue row for g<2
    if (g < 2) {
        if (act) {
            hold = h0[(b0 + erow) * N_REC + rl];
            hs[erow][ws] = hold;
            dr = g_drive[(unsigned)(b0 + erow) * (unsigned)N_REC + (unsigned)rl];
        }
    }
    __syncthreads();

    float* outp = out + (size_t)(b0 + erow) * (TSTEPS * N_REC) + rl;
    const float* h0p = &hs[0][g * 56];
    const float* h1p = &hs[1][g * 56];
    const ulonglong2* ha = reinterpret_cast<const ulonglong2*>(h0p);
    const ulonglong2* hb = reinterpret_cast<const ulonglong2*>(h1p);

    for (int t = 0; t < TSTEPS; ++t) {
        // ---- partial dot over this group's 50-wide k-slice, both rows ----
        ull a = 0ull, c = 0ull;
#pragma unroll
        for (int j = 0; j < 12; ++j) {
            ulonglong2 va = ha[j];      // broadcast: warp-uniform address
            ulonglong2 vb = hb[j];
            a = ffma2(w[2 * j],     va.x, a);
            a = ffma2(w[2 * j + 1], va.y, a);
            c = ffma2(w[2 * j],     vb.x, c);
            c = ffma2(w[2 * j + 1], vb.y, c);
        }
        {   // tail: slice floats 48,49
            a = ffma2(w[24], reinterpret_cast<const ull*>(h0p)[24], a);
            c = ffma2(w[24], reinterpret_cast<const ull*>(h1p)[24], c);
        }
        par[0][g][rl] = lo32f(a) + hi32f(a);
        par[1][g][rl] = lo32f(c) + hi32f(c);
        __syncthreads();

        // ---- epilogue: group g<2 updates batch row b0+g ----
        if (g < 2) {
            float s = ((par[erow][0][rl] + par[erow][1][rl]) +
                       (par[erow][2][rl] + par[erow][3][rl])) + dr.x;
            // tanh(s) = 1 - 2/(exp(2s)+1)
            float e = __expf(s + s);
            float rate = 1.0f - __fdividef(2.0f, e + 1.0f);
            hold = fmaf(0.1f, (rate - hold) + dr.y, hold);
            if (act) {
                hs[erow][ws] = hold;
                outp[t * N_REC] = hold;
                unsigned tn = (t < TSTEPS - 1) ? (unsigned)(t + 1) : (unsigned)(TSTEPS - 1);
                dr = g_drive[(tn * BATCH + (unsigned)(b0 + erow)) * (unsigned)N_REC
                             + (unsigned)rl];
            }
        }
        __syncthreads();
    }
}

// ---------------------------------------------------------------------------
extern "C" void kernel_launch(void* const* d_in, const int* in_sizes, int n_in,
                              void* d_out, int out_size) {
    const float* x     = (const float*)d_in[0];   // [256,1000,10]
    const float* h0    = (const float*)d_in[1];   // [256,200]
    const float* W_inp = (const float*)d_in[2];   // [200,10]
    const float* W_rec = (const float*)d_in[3];   // [200,200]
    const float* b_rec = (const float*)d_in[4];   // [200]
    float* out = (float*)d_out;                   // [256,1000,200]

    gen_drive_kernel<<<TOTAL_ELEMS / 256u, 256>>>(x, W_inp, b_rec);
    rnn_kernel<<<BATCH / 2, 896>>>(h0, W_rec, out);
}

// round 14
// speedup vs baseline: 1.7166x; 1.0955x over previous
#include <cuda_runtime.h>

typedef unsigned long long ull;

#define N_REC   200
#define N_INP   10
#define BATCH   256
#define TSTEPS  1000
#define TOTAL_ELEMS 51200000u   // T*B*N

// drive[t][b][r] = { inp_term(t,b,r),  0.01f * normal(t,b,r) }
static __device__ float2 g_drive[TOTAL_ELEMS];

// ---------------------------------------------------------------------------
// helpers
// ---------------------------------------------------------------------------
__device__ __forceinline__ ull ffma2(ull a, ull b, ull c) {
    ull d;
    asm("fma.rn.f32x2 %0, %1, %2, %3;" : "=l"(d) : "l"(a), "l"(b), "l"(c));
    return d;
}
__device__ __forceinline__ float lo32f(ull v) { return __uint_as_float((unsigned)v); }
__device__ __forceinline__ float hi32f(ull v) { return __uint_as_float((unsigned)(v >> 32)); }

__device__ __forceinline__ unsigned rotl32(unsigned v, int s) {
    return __funnelshift_l(v, v, s);
}

// Threefry-2x32/20, key=(0,42), partitionable: counter=(0,p), out = x0^x1.
__device__ __forceinline__ unsigned threefry_bits(unsigned p) {
    const unsigned k0 = 0u;
    const unsigned k1 = 42u;
    const unsigned k2 = 0x1BD11BDAu ^ 0u ^ 42u;
    unsigned x0 = 0u + k0;
    unsigned x1 = p + k1;
#define TFR(rr) { x0 += x1; x1 = rotl32(x1, rr); x1 ^= x0; }
    TFR(13) TFR(15) TFR(26) TFR(6)   x0 += k1; x1 += k2 + 1u;
    TFR(17) TFR(29) TFR(16) TFR(24)  x0 += k2; x1 += k0 + 2u;
    TFR(13) TFR(15) TFR(26) TFR(6)   x0 += k0; x1 += k1 + 3u;
    TFR(17) TFR(29) TFR(16) TFR(24)  x0 += k1; x1 += k2 + 4u;
    TFR(13) TFR(15) TFR(26) TFR(6)   x0 += k2; x1 += k0 + 5u;
#undef TFR
    return x0 ^ x1;
}

// ---------------------------------------------------------------------------
// Pre-kernel: drive[p] = (x·W_inp[r]+b_rec[r], 0.01*N(0,1)).
// x and W_inp rows loaded as float2 (both 8B-aligned: 40B row stride).
// ---------------------------------------------------------------------------
__global__ void gen_drive_kernel(const float* __restrict__ x,
                                 const float* __restrict__ W_inp,
                                 const float* __restrict__ b_rec) {
    unsigned p = blockIdx.x * blockDim.x + threadIdx.x;
    if (p >= TOTAL_ELEMS) return;

    unsigned bits = threefry_bits(p);
    float f = __uint_as_float((bits >> 9) | 0x3f800000u) - 1.0f;   // [0,1)
    const float lo = __uint_as_float(0xbf7fffffu);                 // nextafter(-1,0)
    float u = fmaf(f, 2.0f, lo);
    u = fmaxf(u, lo);
    float n = __uint_as_float(0x3fb504f3u) * erfinvf(u);           // sqrt(2)*erfinv

    unsigned r  = p % 200u;
    unsigned bt = p / 200u;
    unsigned b  = bt & 255u;
    unsigned t  = bt >> 8;
    const float2* xr = reinterpret_cast<const float2*>(
                           x + (b * (unsigned)TSTEPS + t) * (unsigned)N_INP);
    const float2* wr = reinterpret_cast<const float2*>(W_inp + r * (unsigned)N_INP);
    float inp = __ldg(b_rec + r);
#pragma unroll
    for (int i = 0; i < N_INP / 2; ++i) {
        float2 xv = __ldg(xr + i);
        float2 wv = __ldg(wr + i);
        inp = fmaf(xv.x, wv.x, inp);
        inp = fmaf(xv.y, wv.y, inp);
    }

    g_drive[p] = make_float2(inp, 0.01f * n);
}

// ---------------------------------------------------------------------------
// Main persistent RNN kernel: 128 blocks x 896 threads (28 warps).
// 4 warp-aligned k-groups of 7 warps: g = tid/224, lane rl = tid%224.
// Lane holds W_rec[rl, g*50..+50) in 25 ull regs. h in 56-float padded slices
// (16B aligned) -> every inner LDS is a warp-uniform broadcast.
// Sync via producer/consumer named barriers:
//   bar 1: par ready   (g2,g3 arrive non-blocking; g0,g1 sync)
//   bar 2: hs ready    (everyone syncs)
// STG out / LDG drive issued AFTER bar 2 (overlap next dot phase).
// ---------------------------------------------------------------------------
__global__ __launch_bounds__(896, 1)
void rnn_kernel(const float* __restrict__ h0,
                const float* __restrict__ Wrec,
                float* __restrict__ out) {
    __shared__ __align__(16) float hs[2][224];       // [row][slice(rl/50)*56 + rl%50]
    __shared__ __align__(16) float par[2][4][224];   // [row][kgroup][rl]

    const int tid = threadIdx.x;
    const int g   = tid / 224;          // k-group 0..3 (7 warps each)
    const int rl  = tid - g * 224;      // 0..223
    const bool act = (rl < N_REC);
    const int rc  = act ? rl : (N_REC - 1);
    const int b0  = blockIdx.x * 2;

    // ---- W_rec[rc, g*50 .. +50) -> 25 ull regs ----
    ull w[25];
    {
        const ull* wp = reinterpret_cast<const ull*>(Wrec + rc * N_REC + g * 50);
#pragma unroll
        for (int j = 0; j < 25; ++j) w[j] = wp[j];
    }

    const int ws = (rc / 50) * 56 + (rc % 50);   // write slot in padded layout

    // ---- init: groups 0/1 own batch rows b0+0 / b0+1 ----
    float hold = 0.f;
    float2 dr = make_float2(0.f, 0.f);
    if (g < 2 && act) {
        hold = h0[(b0 + g) * N_REC + rl];
        hs[g][ws] = hold;
        dr = g_drive[(unsigned)(b0 + g) * (unsigned)N_REC + (unsigned)rl];
    }
    __syncthreads();

    // epilogue-only pointers (valid for g<2, act)
    float* outp = out + (size_t)(b0 + (g < 2 ? g : 0)) * (TSTEPS * N_REC) + rl;
    const float2* drv = g_drive + ((size_t)BATCH + (size_t)(b0 + (g < 2 ? g : 0)))
                                  * (size_t)N_REC + (size_t)rc;   // t=1 base

    const float* h0p = &hs[0][g * 56];
    const float* h1p = &hs[1][g * 56];
    const ulonglong2* ha = reinterpret_cast<const ulonglong2*>(h0p);
    const ulonglong2* hb = reinterpret_cast<const ulonglong2*>(h1p);

    for (int t = 0; t < TSTEPS; ++t) {
        // ---- partial dot over this group's 50-wide k-slice, both rows ----
        ull a = 0ull, c = 0ull;
#pragma unroll
        for (int j = 0; j < 12; ++j) {
            ulonglong2 va = ha[j];      // warp-uniform broadcast
            ulonglong2 vb = hb[j];
            a = ffma2(w[2 * j],     va.x, a);
            a = ffma2(w[2 * j + 1], va.y, a);
            c = ffma2(w[2 * j],     vb.x, c);
            c = ffma2(w[2 * j + 1], vb.y, c);
        }
        {   // tail: slice floats 48,49
            a = ffma2(w[24], reinterpret_cast<const ull*>(h0p)[24], a);
            c = ffma2(w[24], reinterpret_cast<const ull*>(h1p)[24], c);
        }
        par[0][g][rl] = lo32f(a) + hi32f(a);
        par[1][g][rl] = lo32f(c) + hi32f(c);

        if (g < 2) {
            asm volatile("bar.sync 1, 896;" ::: "memory");   // wait: par ready
            float s = ((par[g][0][rl] + par[g][1][rl]) +
                       (par[g][2][rl] + par[g][3][rl])) + dr.x;
            // tanh(s) = 1 - 2/(exp(2s)+1)
            float e = __expf(s + s);
            float rate = 1.0f - __fdividef(2.0f, e + 1.0f);
            hold = fmaf(0.1f, (rate - hold) + dr.y, hold);
            if (act) hs[g][ws] = hold;
            asm volatile("bar.sync 2, 896;" ::: "memory");   // hs ready
            // off-critical-path: output store + next-step drive prefetch
            if (act) {
                *outp = hold;
                outp += N_REC;
                dr = *drv;                       // drive for t+1
            }
            if (t < TSTEPS - 2) drv += (size_t)BATCH * N_REC;
        } else {
            asm volatile("bar.arrive 1, 896;" ::: "memory"); // producer arrive
            asm volatile("bar.sync 2, 896;"   ::: "memory"); // wait: hs ready
        }
    }
}

// ---------------------------------------------------------------------------
extern "C" void kernel_launch(void* const* d_in, const int* in_sizes, int n_in,
                              void* d_out, int out_size) {
    const float* x     = (const float*)d_in[0];   // [256,1000,10]
    const float* h0    = (const float*)d_in[1];   // [256,200]
    const float* W_inp = (const float*)d_in[2];   // [200,10]
    const float* W_rec = (const float*)d_in[3];   // [200,200]
    const float* b_rec = (const float*)d_in[4];   // [200]
    float* out = (float*)d_out;                   // [256,1000,200]

    gen_drive_kernel<<<TOTAL_ELEMS / 256u, 256>>>(x, W_inp, b_rec);
    rnn_kernel<<<BATCH / 2, 896>>>(h0, W_rec, out);
}

// round 15
// speedup vs baseline: 1.7168x; 1.0001x over previous
#include <cuda_runtime.h>

typedef unsigned long long ull;

#define N_REC   200
#define N_INP   10
#define BATCH   256
#define TSTEPS  1000
#define TOTAL_ELEMS 51200000u   // T*B*N

// drive[t][b][r] = { inp_term(t,b,r),  0.01f * normal(t,b,r) }
static __device__ float2 g_drive[TOTAL_ELEMS];

// ---------------------------------------------------------------------------
// helpers
// ---------------------------------------------------------------------------
__device__ __forceinline__ ull ffma2(ull a, ull b, ull c) {
    ull d;
    asm("fma.rn.f32x2 %0, %1, %2, %3;" : "=l"(d) : "l"(a), "l"(b), "l"(c));
    return d;
}
__device__ __forceinline__ float lo32f(ull v) { return __uint_as_float((unsigned)v); }
__device__ __forceinline__ float hi32f(ull v) { return __uint_as_float((unsigned)(v >> 32)); }

__device__ __forceinline__ unsigned rotl32(unsigned v, int s) {
    return __funnelshift_l(v, v, s);
}

// Threefry-2x32/20, key=(0,42), partitionable: counter=(0,p), out = x0^x1.
__device__ __forceinline__ unsigned threefry_bits(unsigned p) {
    const unsigned k0 = 0u;
    const unsigned k1 = 42u;
    const unsigned k2 = 0x1BD11BDAu ^ 0u ^ 42u;
    unsigned x0 = 0u + k0;
    unsigned x1 = p + k1;
#define TFR(rr) { x0 += x1; x1 = rotl32(x1, rr); x1 ^= x0; }
    TFR(13) TFR(15) TFR(26) TFR(6)   x0 += k1; x1 += k2 + 1u;
    TFR(17) TFR(29) TFR(16) TFR(24)  x0 += k2; x1 += k0 + 2u;
    TFR(13) TFR(15) TFR(26) TFR(6)   x0 += k0; x1 += k1 + 3u;
    TFR(17) TFR(29) TFR(16) TFR(24)  x0 += k1; x1 += k2 + 4u;
    TFR(13) TFR(15) TFR(26) TFR(6)   x0 += k2; x1 += k0 + 5u;
#undef TFR
    return x0 ^ x1;
}

// ---------------------------------------------------------------------------
// Pre-kernel: drive[p] = (x·W_inp[r]+b_rec[r], 0.01*N(0,1)).
// x and W_inp rows loaded as float2 (both 8B-aligned: 40B row stride).
// ---------------------------------------------------------------------------
__global__ void gen_drive_kernel(const float* __restrict__ x,
                                 const float* __restrict__ W_inp,
                                 const float* __restrict__ b_rec) {
    unsigned p = blockIdx.x * blockDim.x + threadIdx.x;
    if (p >= TOTAL_ELEMS) return;

    unsigned bits = threefry_bits(p);
    float f = __uint_as_float((bits >> 9) | 0x3f800000u) - 1.0f;   // [0,1)
    const float lo = __uint_as_float(0xbf7fffffu);                 // nextafter(-1,0)
    float u = fmaf(f, 2.0f, lo);
    u = fmaxf(u, lo);
    float n = __uint_as_float(0x3fb504f3u) * erfinvf(u);           // sqrt(2)*erfinv

    unsigned r  = p % 200u;
    unsigned bt = p / 200u;
    unsigned b  = bt & 255u;
    unsigned t  = bt >> 8;
    const float2* xr = reinterpret_cast<const float2*>(
                           x + (b * (unsigned)TSTEPS + t) * (unsigned)N_INP);
    const float2* wr = reinterpret_cast<const float2*>(W_inp + r * (unsigned)N_INP);
    float inp = __ldg(b_rec + r);
#pragma unroll
    for (int i = 0; i < N_INP / 2; ++i) {
        float2 xv = __ldg(xr + i);
        float2 wv = __ldg(wr + i);
        inp = fmaf(xv.x, wv.x, inp);
        inp = fmaf(xv.y, wv.y, inp);
    }

    g_drive[p] = make_float2(inp, 0.01f * n);
}

// ---------------------------------------------------------------------------
// Main persistent RNN kernel: 128 blocks x 896 threads (28 warps).
// 4 warp-aligned k-groups of 7 warps: g = tid/224, lane rl = tid%224.
// Lane holds W_rec[rl, g*50..+50) in 25 ull regs. h in 56-float padded slices
// (16B aligned) -> every inner LDS is a warp-uniform broadcast.
// Sync via producer/consumer named barriers:
//   bar 1: par ready   (g2,g3 arrive non-blocking; g0,g1 sync)
//   bar 2: hs ready    (everyone syncs)
// STG out / LDG drive issued AFTER bar 2 (overlap next dot phase).
// ---------------------------------------------------------------------------
__global__ __launch_bounds__(896, 1)
void rnn_kernel(const float* __restrict__ h0,
                const float* __restrict__ Wrec,
                float* __restrict__ out) {
    __shared__ __align__(16) float hs[2][224];       // [row][slice(rl/50)*56 + rl%50]
    __shared__ __align__(16) float par[2][4][224];   // [row][kgroup][rl]

    const int tid = threadIdx.x;
    const int g   = tid / 224;          // k-group 0..3 (7 warps each)
    const int rl  = tid - g * 224;      // 0..223
    const bool act = (rl < N_REC);
    const int rc  = act ? rl : (N_REC - 1);
    const int b0  = blockIdx.x * 2;

    // ---- W_rec[rc, g*50 .. +50) -> 25 ull regs ----
    ull w[25];
    {
        const ull* wp = reinterpret_cast<const ull*>(Wrec + rc * N_REC + g * 50);
#pragma unroll
        for (int j = 0; j < 25; ++j) w[j] = wp[j];
    }

    const int ws = (rc / 50) * 56 + (rc % 50);   // write slot in padded layout

    // ---- init: groups 0/1 own batch rows b0+0 / b0+1 ----
    float hold = 0.f;
    float2 dr = make_float2(0.f, 0.f);
    if (g < 2 && act) {
        hold = h0[(b0 + g) * N_REC + rl];
        hs[g][ws] = hold;
        dr = g_drive[(unsigned)(b0 + g) * (unsigned)N_REC + (unsigned)rl];
    }
    __syncthreads();

    // epilogue-only pointers (valid for g<2, act)
    float* outp = out + (size_t)(b0 + (g < 2 ? g : 0)) * (TSTEPS * N_REC) + rl;
    const float2* drv = g_drive + ((size_t)BATCH + (size_t)(b0 + (g < 2 ? g : 0)))
                                  * (size_t)N_REC + (size_t)rc;   // t=1 base

    const float* h0p = &hs[0][g * 56];
    const float* h1p = &hs[1][g * 56];
    const ulonglong2* ha = reinterpret_cast<const ulonglong2*>(h0p);
    const ulonglong2* hb = reinterpret_cast<const ulonglong2*>(h1p);

    for (int t = 0; t < TSTEPS; ++t) {
        // ---- partial dot over this group's 50-wide k-slice, both rows ----
        ull a = 0ull, c = 0ull;
#pragma unroll
        for (int j = 0; j < 12; ++j) {
            ulonglong2 va = ha[j];      // warp-uniform broadcast
            ulonglong2 vb = hb[j];
            a = ffma2(w[2 * j],     va.x, a);
            a = ffma2(w[2 * j + 1], va.y, a);
            c = ffma2(w[2 * j],     vb.x, c);
            c = ffma2(w[2 * j + 1], vb.y, c);
        }
        {   // tail: slice floats 48,49
            a = ffma2(w[24], reinterpret_cast<const ull*>(h0p)[24], a);
            c = ffma2(w[24], reinterpret_cast<const ull*>(h1p)[24], c);
        }
        par[0][g][rl] = lo32f(a) + hi32f(a);
        par[1][g][rl] = lo32f(c) + hi32f(c);

        if (g < 2) {
            asm volatile("bar.sync 1, 896;" ::: "memory");   // wait: par ready
            float s = ((par[g][0][rl] + par[g][1][rl]) +
                       (par[g][2][rl] + par[g][3][rl])) + dr.x;
            // tanh(s) = 1 - 2/(exp(2s)+1)
            float e = __expf(s + s);
            float rate = 1.0f - __fdividef(2.0f, e + 1.0f);
            hold = fmaf(0.1f, (rate - hold) + dr.y, hold);
            if (act) hs[g][ws] = hold;
            asm volatile("bar.sync 2, 896;" ::: "memory");   // hs ready
            // off-critical-path: output store + next-step drive prefetch
            if (act) {
                *outp = hold;
                outp += N_REC;
                dr = *drv;                       // drive for t+1
            }
            if (t < TSTEPS - 2) drv += (size_t)BATCH * N_REC;
        } else {
            asm volatile("bar.arrive 1, 896;" ::: "memory"); // producer arrive
            asm volatile("bar.sync 2, 896;"   ::: "memory"); // wait: hs ready
        }
    }
}

// ---------------------------------------------------------------------------
extern "C" void kernel_launch(void* const* d_in, const int* in_sizes, int n_in,
                              void* d_out, int out_size) {
    const float* x     = (const float*)d_in[0];   // [256,1000,10]
    const float* h0    = (const float*)d_in[1];   // [256,200]
    const float* W_inp = (const float*)d_in[2];   // [200,10]
    const float* W_rec = (const float*)d_in[3];   // [200,200]
    const float* b_rec = (const float*)d_in[4];   // [200]
    float* out = (float*)d_out;                   // [256,1000,200]

    gen_drive_kernel<<<TOTAL_ELEMS / 256u, 256>>>(x, W_inp, b_rec);
    rnn_kernel<<<BATCH / 2, 896>>>(h0, W_rec, out);
}